// round 3
// baseline (speedup 1.0000x reference)
#include <cuda_runtime.h>
#include <math.h>

#define DHID 128
#define DOUTF 32

static const int NMAX = 50000;
static const int EMAX = 600000;

// ---- scratch (device globals: allocation-free per harness rules) ----
__device__ float g_bufA[(size_t)NMAX * DHID];
__device__ float g_bufB[(size_t)NMAX * DHID];
__device__ float g_dinv[NMAX];
__device__ int   g_cnt[NMAX];
__device__ int   g_rowptr[NMAX + 1];
__device__ int   g_fill[NMAX];
__device__ int   g_col[EMAX];

// ---------------------------------------------------------------
// graph preprocessing
// ---------------------------------------------------------------
__global__ void k_zero_cnt(int n) {
    int i = blockIdx.x * blockDim.x + threadIdx.x;
    if (i < n) g_cnt[i] = 0;
}

__global__ void k_count(const int* __restrict__ dst, int e) {
    int i = blockIdx.x * blockDim.x + threadIdx.x;
    if (i < e) atomicAdd(&g_cnt[dst[i]], 1);
}

__global__ void k_dinv(int n) {
    int i = blockIdx.x * blockDim.x + threadIdx.x;
    if (i < n) g_dinv[i] = rsqrtf((float)(g_cnt[i] + 1));  // +1 self-loop
}

// single-block exclusive scan of g_cnt -> g_rowptr / g_fill
__global__ void k_scan(int n) {
    __shared__ int ps[1024];
    int t = threadIdx.x;
    int chunk = (n + 1023) >> 10;
    int base = t * chunk;
    int end = base + chunk; if (end > n) end = n;
    int s = 0;
    for (int i = base; i < end; i++) s += g_cnt[i];
    ps[t] = s;
    __syncthreads();
    // Hillis-Steele inclusive scan
    for (int off = 1; off < 1024; off <<= 1) {
        int v = ps[t] + ((t >= off) ? ps[t - off] : 0);
        __syncthreads();
        ps[t] = v;
        __syncthreads();
    }
    int run = (t == 0) ? 0 : ps[t - 1];
    for (int i = base; i < end; i++) {
        g_rowptr[i] = run;
        g_fill[i]   = run;
        run += g_cnt[i];
    }
    if (t == 0) g_rowptr[n] = ps[1023];
}

__global__ void k_fill(const int* __restrict__ src, const int* __restrict__ dst, int e) {
    int i = blockIdx.x * blockDim.x + threadIdx.x;
    if (i < e) {
        int p = atomicAdd(&g_fill[dst[i]], 1);
        g_col[p] = src[i];
    }
}

// ---------------------------------------------------------------
// GEMM: Y[r][j] = (sum_k X[r][k]*W[k][j]) * (SCALE ? dinv[r] : 1) (+ bias[j] if BIAS)
// BM = 64 rows per block, full K=128.
// ---------------------------------------------------------------
#define XSTR 132  // padded smem row stride (floats), 16B-aligned, kills bank conflicts

template <int FOUT, bool SCALE, bool BIAS>
__global__ void __launch_bounds__(256) k_gemm(const float* __restrict__ X,
                                              const float* __restrict__ W,
                                              const float* __restrict__ bias,
                                              float* __restrict__ Y, int n) {
    const int CG  = FOUT / 4;     // col groups (float4 each)
    const int RG  = 256 / CG;     // row groups
    const int RPT = 64 / RG;      // rows per thread

    extern __shared__ float smem[];
    float* Xs = smem;                 // 64 x XSTR
    float* Ws = smem + 64 * XSTR;     // 128 x FOUT

    int tid  = threadIdx.x;
    int row0 = blockIdx.x * 64;

    // stage W
    for (int i = tid; i < DHID * FOUT / 4; i += 256)
        ((float4*)Ws)[i] = ((const float4*)W)[i];

    // stage X tile (zero-pad OOB rows)
    for (int i = tid; i < 64 * (DHID / 4); i += 256) {
        int r = i / (DHID / 4);
        int c = i % (DHID / 4);
        float4 v = make_float4(0.f, 0.f, 0.f, 0.f);
        if (row0 + r < n) v = ((const float4*)X)[(size_t)(row0 + r) * (DHID / 4) + c];
        ((float4*)(Xs + r * XSTR))[c] = v;
    }
    __syncthreads();

    int cg = tid % CG;
    int rg = tid / CG;
    const float* xbase = Xs + rg * RPT * XSTR;

    float4 acc[RPT];
#pragma unroll
    for (int m = 0; m < RPT; m++) acc[m] = make_float4(0.f, 0.f, 0.f, 0.f);

#pragma unroll 8
    for (int k = 0; k < DHID; k++) {
        float4 w = ((const float4*)Ws)[k * CG + cg];
#pragma unroll
        for (int m = 0; m < RPT; m++) {
            float xv = xbase[m * XSTR + k];
            acc[m].x = fmaf(xv, w.x, acc[m].x);
            acc[m].y = fmaf(xv, w.y, acc[m].y);
            acc[m].z = fmaf(xv, w.z, acc[m].z);
            acc[m].w = fmaf(xv, w.w, acc[m].w);
        }
    }

#pragma unroll
    for (int m = 0; m < RPT; m++) {
        int r = row0 + rg * RPT + m;
        if (r < n) {
            float4 v = acc[m];
            if (SCALE) {
                float s = g_dinv[r];
                v.x *= s; v.y *= s; v.z *= s; v.w *= s;
            }
            if (BIAS) {
                float4 b = ((const float4*)bias)[cg];
                v.x += b.x; v.y += b.y; v.z += b.z; v.w += b.w;
            }
            ((float4*)Y)[(size_t)r * CG + cg] = v;
        }
    }
}

// ---------------------------------------------------------------
// Aggregation: H[i] = relu(bias + dinv[i] * (T[i] + sum_{e in CSR[i]} T[col[e]]))
// one warp per node, lane = one float4 of the 128-wide row
// ---------------------------------------------------------------
__global__ void __launch_bounds__(256) k_agg(const float4* __restrict__ T4,
                                             const float* __restrict__ bias,
                                             float4* __restrict__ H4, int n) {
    int gw   = (blockIdx.x * blockDim.x + threadIdx.x) >> 5;
    int lane = threadIdx.x & 31;
    if (gw >= n) return;

    float4 a = T4[(size_t)gw * 32 + lane];  // self-loop contribution
    int beg = g_rowptr[gw];
    int end = g_rowptr[gw + 1];
    int e = beg;
    int sn = (e < end) ? g_col[e] : 0;      // prefetch next index
    while (e < end) {
        int s = sn;
        ++e;
        sn = (e < end) ? g_col[e] : 0;
        float4 v = T4[(size_t)s * 32 + lane];
        a.x += v.x; a.y += v.y; a.z += v.z; a.w += v.w;
    }
    float d = g_dinv[gw];
    float4 b = ((const float4*)bias)[lane];
    float4 o;
    o.x = fmaxf(fmaf(d, a.x, b.x), 0.f);
    o.y = fmaxf(fmaf(d, a.y, b.y), 0.f);
    o.z = fmaxf(fmaf(d, a.z, b.z), 0.f);
    o.w = fmaxf(fmaf(d, a.w, b.w), 0.f);
    H4[(size_t)gw * 32 + lane] = o;
}

// ---------------------------------------------------------------
extern "C" void kernel_launch(void* const* d_in, const int* in_sizes, int n_in,
                              void* d_out, int out_size) {
    const float* x  = (const float*)d_in[0];
    const int*   ei = (const int*)d_in[1];
    const float* W1 = (const float*)d_in[2];
    const float* b1 = (const float*)d_in[3];
    const float* W2 = (const float*)d_in[4];
    const float* b2 = (const float*)d_in[5];
    const float* W3 = (const float*)d_in[6];
    const float* b3 = (const float*)d_in[7];
    const float* Wl = (const float*)d_in[8];
    const float* bl = (const float*)d_in[9];
    float* out = (float*)d_out;

    int N = in_sizes[0] / DHID;
    int E = in_sizes[1] / 2;
    const int* src = ei;
    const int* dst = ei + E;

    float *bufA, *bufB;
    cudaGetSymbolAddress((void**)&bufA, g_bufA);
    cudaGetSymbolAddress((void**)&bufB, g_bufB);

    const int SMEM_L = (64 * XSTR + DHID * DHID) * 4;   // 99328 B
    const int SMEM_F = (64 * XSTR + DHID * DOUTF) * 4;  // 50176 B
    cudaFuncSetAttribute(k_gemm<DHID, true, false>,
                         cudaFuncAttributeMaxDynamicSharedMemorySize, SMEM_L);
    cudaFuncSetAttribute(k_gemm<DOUTF, false, true>,
                         cudaFuncAttributeMaxDynamicSharedMemorySize, SMEM_F);

    int nb  = (N + 255) / 256;
    int ebl = (E + 255) / 256;
    int gb  = (N + 63) / 64;
    int ab  = ((size_t)N * 32 + 255) / 256;

    // --- build normalized CSR ---
    k_zero_cnt<<<nb, 256>>>(N);
    k_count<<<ebl, 256>>>(dst, E);
    k_dinv<<<nb, 256>>>(N);
    k_scan<<<1, 1024>>>(N);
    k_fill<<<ebl, 256>>>(src, dst, E);

    // --- layer 1 ---
    k_gemm<DHID, true, false><<<gb, 256, SMEM_L>>>(x, W1, nullptr, bufB, N);
    k_agg<<<ab, 256>>>((const float4*)bufB, b1, (float4*)bufA, N);
    // --- layer 2 ---
    k_gemm<DHID, true, false><<<gb, 256, SMEM_L>>>(bufA, W2, nullptr, bufB, N);
    k_agg<<<ab, 256>>>((const float4*)bufB, b2, (float4*)bufA, N);
    // --- layer 3 ---
    k_gemm<DHID, true, false><<<gb, 256, SMEM_L>>>(bufA, W3, nullptr, bufB, N);
    k_agg<<<ab, 256>>>((const float4*)bufB, b3, (float4*)bufA, N);
    // --- output projection ---
    k_gemm<DOUTF, false, true><<<gb, 256, SMEM_F>>>(bufA, Wl, bl, out, N);
}

// round 7
// speedup vs baseline: 1.4021x; 1.4021x over previous
#include <cuda_runtime.h>
#include <math.h>

#define DHID 128
#define DOUTF 32
#define SCANB 128

static const int NMAX = 50000;
static const int EMAX = 600000;

// ---- scratch (device globals: allocation-free per harness rules) ----
__device__ float g_bufA[(size_t)NMAX * DHID];
__device__ float g_bufB[(size_t)NMAX * DHID];
__device__ float g_dinv[NMAX];
__device__ int   g_cnt[NMAX];
__device__ int   g_rowptr[NMAX + 1];
__device__ int   g_fill[NMAX];
__device__ int   g_col[EMAX];
__device__ int   g_bsum[SCANB];

// ---- packed f32x2 helpers (Blackwell FFMA2: PTX-only, ptxas won't auto-fuse) ----
__device__ __forceinline__ unsigned long long pack2(float lo, float hi) {
    unsigned long long r;
    asm("mov.b64 %0, {%1, %2};" : "=l"(r) : "f"(lo), "f"(hi));
    return r;
}
__device__ __forceinline__ void unpack2(unsigned long long v, float& lo, float& hi) {
    asm("mov.b64 {%0, %1}, %2;" : "=f"(lo), "=f"(hi) : "l"(v));
}
__device__ __forceinline__ void ffma2(unsigned long long& d,
                                      unsigned long long a, unsigned long long b) {
    asm("fma.rn.f32x2 %0, %1, %2, %0;" : "+l"(d) : "l"(a), "l"(b));
}

// ---------------------------------------------------------------
// graph preprocessing
// ---------------------------------------------------------------
__global__ void k_zero_cnt(int n) {
    int i = blockIdx.x * blockDim.x + threadIdx.x;
    if (i < n) g_cnt[i] = 0;
}

__global__ void k_count(const int* __restrict__ dst, int e) {
    int i = blockIdx.x * blockDim.x + threadIdx.x;
    if (i < e) atomicAdd(&g_cnt[dst[i]], 1);
}

// pass 1: per-block chunk sums of g_cnt (+ fused dinv computation)
__global__ void __launch_bounds__(256) k_scan1(int n) {
    __shared__ int red[256];
    int b = blockIdx.x;
    int ch = (n + SCANB - 1) / SCANB;
    int beg = b * ch;
    int end = beg + ch; if (end > n) end = n;
    int t = threadIdx.x;
    int s = 0;
    for (int i = beg + t; i < end; i += 256) {
        int c = g_cnt[i];
        s += c;
        g_dinv[i] = rsqrtf((float)(c + 1));  // +1 self-loop
    }
    red[t] = s;
    __syncthreads();
    for (int off = 128; off > 0; off >>= 1) {
        if (t < off) red[t] += red[t + off];
        __syncthreads();
    }
    if (t == 0) g_bsum[b] = red[0];
}

// pass 2: each block computes its global offset from g_bsum (redundant
// 128-element reduction, cheaper than an extra kernel), then scans its
// chunk and writes rowptr/fill.
__global__ void __launch_bounds__(256) k_scan2(int n) {
    __shared__ int sps[256];
    __shared__ int sboff[2];  // [0]=block offset, [1]=grand total
    int b = blockIdx.x, t = threadIdx.x;
    int ch = (n + SCANB - 1) / SCANB;
    int beg = b * ch;
    int end = beg + ch; if (end > n) end = n;

    if (t < 32) {
        int v = 0, g = 0;
        for (int i = t; i < SCANB; i += 32) {
            int bs = g_bsum[i];
            if (i < b) v += bs;
            g += bs;
        }
        for (int o = 16; o > 0; o >>= 1) {
            v += __shfl_down_sync(0xffffffffu, v, o);
            g += __shfl_down_sync(0xffffffffu, g, o);
        }
        if (t == 0) { sboff[0] = v; sboff[1] = g; }
    }

    // per-thread contiguous sub-chunk sum
    int sub = (ch + 255) / 256;
    int tb = beg + t * sub;
    int te = tb + sub; if (te > end) te = end;
    int s = 0;
    for (int i = tb; i < te; i++) s += g_cnt[i];
    sps[t] = s;
    __syncthreads();
    // Hillis-Steele inclusive scan over 256 thread sums
    for (int off = 1; off < 256; off <<= 1) {
        int v = sps[t] + ((t >= off) ? sps[t - off] : 0);
        __syncthreads();
        sps[t] = v;
        __syncthreads();
    }
    int run = sboff[0] + ((t > 0) ? sps[t - 1] : 0);
    for (int i = tb; i < te; i++) {
        g_rowptr[i] = run;
        g_fill[i]   = run;
        run += g_cnt[i];
    }
    if (b == 0 && t == 0) g_rowptr[n] = sboff[1];
}

__global__ void k_fill(const int* __restrict__ src, const int* __restrict__ dst, int e) {
    int i = blockIdx.x * blockDim.x + threadIdx.x;
    if (i < e) {
        int p = atomicAdd(&g_fill[dst[i]], 1);
        g_col[p] = src[i];
    }
}

// ---------------------------------------------------------------
// GEMM: Y[r][j] = (sum_k X[r][k]*W[k][j]) * (SCALE ? dinv[r] : 1) (+ bias[j] if BIAS)
// BM = 64 rows per block, full K=128. Inner loop uses packed fma.rn.f32x2.
// ---------------------------------------------------------------
#define XSTR 132  // padded smem row stride (floats), 16B-aligned, kills bank conflicts

template <int FOUT, bool SCALE, bool BIAS>
__global__ void __launch_bounds__(256) k_gemm(const float* __restrict__ X,
                                              const float* __restrict__ W,
                                              const float* __restrict__ bias,
                                              float* __restrict__ Y, int n) {
    const int CG  = FOUT / 4;     // col groups (float4 each)
    const int RG  = 256 / CG;     // row groups
    const int RPT = 64 / RG;      // rows per thread

    extern __shared__ float smem[];
    float* Xs = smem;                 // 64 x XSTR
    float* Ws = smem + 64 * XSTR;     // 128 x FOUT

    int tid  = threadIdx.x;
    int row0 = blockIdx.x * 64;

    // stage W
    for (int i = tid; i < DHID * FOUT / 4; i += 256)
        ((float4*)Ws)[i] = ((const float4*)W)[i];

    // stage X tile (zero-pad OOB rows)
    for (int i = tid; i < 64 * (DHID / 4); i += 256) {
        int r = i / (DHID / 4);
        int c = i % (DHID / 4);
        float4 v = make_float4(0.f, 0.f, 0.f, 0.f);
        if (row0 + r < n) v = ((const float4*)X)[(size_t)(row0 + r) * (DHID / 4) + c];
        ((float4*)(Xs + r * XSTR))[c] = v;
    }
    __syncthreads();

    int cg = tid % CG;
    int rg = tid / CG;
    const float* xbase = Xs + rg * RPT * XSTR;

    // packed accumulators: acc2[m][0] = {col0,col1}, acc2[m][1] = {col2,col3}
    unsigned long long acc2[RPT][2];
#pragma unroll
    for (int m = 0; m < RPT; m++) { acc2[m][0] = 0ull; acc2[m][1] = 0ull; }

#pragma unroll 8
    for (int k = 0; k < DHID; k++) {
        float4 w = ((const float4*)Ws)[k * CG + cg];
        unsigned long long w01 = pack2(w.x, w.y);
        unsigned long long w23 = pack2(w.z, w.w);
#pragma unroll
        for (int m = 0; m < RPT; m++) {
            float xv = xbase[m * XSTR + k];
            unsigned long long xp = pack2(xv, xv);
            ffma2(acc2[m][0], xp, w01);
            ffma2(acc2[m][1], xp, w23);
        }
    }

#pragma unroll
    for (int m = 0; m < RPT; m++) {
        int r = row0 + rg * RPT + m;
        if (r < n) {
            float4 v;
            unpack2(acc2[m][0], v.x, v.y);
            unpack2(acc2[m][1], v.z, v.w);
            if (SCALE) {
                float s = g_dinv[r];
                v.x *= s; v.y *= s; v.z *= s; v.w *= s;
            }
            if (BIAS) {
                float4 b = ((const float4*)bias)[cg];
                v.x += b.x; v.y += b.y; v.z += b.z; v.w += b.w;
            }
            ((float4*)Y)[(size_t)r * CG + cg] = v;
        }
    }
}

// ---------------------------------------------------------------
// Aggregation: H[i] = relu(bias + dinv[i] * (T[i] + sum_{e in CSR[i]} T[col[e]]))
// one warp per node, lane = one float4 of the 128-wide row
// ---------------------------------------------------------------
__global__ void __launch_bounds__(256) k_agg(const float4* __restrict__ T4,
                                             const float* __restrict__ bias,
                                             float4* __restrict__ H4, int n) {
    int gw   = (blockIdx.x * blockDim.x + threadIdx.x) >> 5;
    int lane = threadIdx.x & 31;
    if (gw >= n) return;

    float4 a = T4[(size_t)gw * 32 + lane];  // self-loop contribution
    int beg = g_rowptr[gw];
    int end = g_rowptr[gw + 1];
    int e = beg;
    int sn = (e < end) ? g_col[e] : 0;      // prefetch next index
    while (e < end) {
        int s = sn;
        ++e;
        sn = (e < end) ? g_col[e] : 0;
        float4 v = T4[(size_t)s * 32 + lane];
        a.x += v.x; a.y += v.y; a.z += v.z; a.w += v.w;
    }
    float d = g_dinv[gw];
    float4 b = ((const float4*)bias)[lane];
    float4 o;
    o.x = fmaxf(fmaf(d, a.x, b.x), 0.f);
    o.y = fmaxf(fmaf(d, a.y, b.y), 0.f);
    o.z = fmaxf(fmaf(d, a.z, b.z), 0.f);
    o.w = fmaxf(fmaf(d, a.w, b.w), 0.f);
    H4[(size_t)gw * 32 + lane] = o;
}

// ---------------------------------------------------------------
extern "C" void kernel_launch(void* const* d_in, const int* in_sizes, int n_in,
                              void* d_out, int out_size) {
    const float* x  = (const float*)d_in[0];
    const int*   ei = (const int*)d_in[1];
    const float* W1 = (const float*)d_in[2];
    const float* b1 = (const float*)d_in[3];
    const float* W2 = (const float*)d_in[4];
    const float* b2 = (const float*)d_in[5];
    const float* W3 = (const float*)d_in[6];
    const float* b3 = (const float*)d_in[7];
    const float* Wl = (const float*)d_in[8];
    const float* bl = (const float*)d_in[9];
    float* out = (float*)d_out;

    int N = in_sizes[0] / DHID;
    int E = in_sizes[1] / 2;
    const int* src = ei;
    const int* dst = ei + E;

    float *bufA, *bufB;
    cudaGetSymbolAddress((void**)&bufA, g_bufA);
    cudaGetSymbolAddress((void**)&bufB, g_bufB);

    const int SMEM_L = (64 * XSTR + DHID * DHID) * 4;   // 99328 B
    const int SMEM_F = (64 * XSTR + DHID * DOUTF) * 4;  // 50176 B
    cudaFuncSetAttribute(k_gemm<DHID, true, false>,
                         cudaFuncAttributeMaxDynamicSharedMemorySize, SMEM_L);
    cudaFuncSetAttribute(k_gemm<DOUTF, false, true>,
                         cudaFuncAttributeMaxDynamicSharedMemorySize, SMEM_F);

    int nb  = (N + 255) / 256;
    int ebl = (E + 255) / 256;
    int gb  = (N + 63) / 64;
    int ab  = ((size_t)N * 32 + 255) / 256;

    // --- build normalized CSR ---
    k_zero_cnt<<<nb, 256>>>(N);
    k_count<<<ebl, 256>>>(dst, E);
    k_scan1<<<SCANB, 256>>>(N);   // chunk sums + dinv
    k_scan2<<<SCANB, 256>>>(N);   // offsets + rowptr/fill
    k_fill<<<ebl, 256>>>(src, dst, E);

    // --- layer 1 ---
    k_gemm<DHID, true, false><<<gb, 256, SMEM_L>>>(x, W1, nullptr, bufB, N);
    k_agg<<<ab, 256>>>((const float4*)bufB, b1, (float4*)bufA, N);
    // --- layer 2 ---
    k_gemm<DHID, true, false><<<gb, 256, SMEM_L>>>(bufA, W2, nullptr, bufB, N);
    k_agg<<<ab, 256>>>((const float4*)bufB, b2, (float4*)bufA, N);
    // --- layer 3 ---
    k_gemm<DHID, true, false><<<gb, 256, SMEM_L>>>(bufA, W3, nullptr, bufB, N);
    k_agg<<<ab, 256>>>((const float4*)bufB, b3, (float4*)bufA, N);
    // --- output projection ---
    k_gemm<DOUTF, false, true><<<gb, 256, SMEM_F>>>(bufA, Wl, bl, out, N);
}